// round 3
// baseline (speedup 1.0000x reference)
#include <cuda_runtime.h>
#include <cstdint>
#include <math.h>

#define IN_DIM  1024
#define OUT_DIM 1024
#define NE      8
#define NTOK    8192
#define KTOT    (NE * IN_DIM)          // 8192
#define BM      128
#define BN      128
#define SA_STRIDE 20                    // floats
#define SB_STRIDE 136                   // floats
#define NCHUNK  513                     // 512 weight chunks + 1 gate/bias chunk
#define STAGES  4

#define SA_STAGE (BM * SA_STRIDE)       // 2560 floats
#define SB_STAGE (16 * SB_STRIDE)       // 2176 floats
#define SMEM_FLOATS (STAGES * SA_STAGE + STAGES * SB_STAGE + BM * NE)
#define SMEM_BYTES  (SMEM_FLOATS * 4)   // 79872

// ---------------- scratch ----------------
__device__ float g_gates[NTOK * NE];                 // softmax gates [N, E]
__device__ float g_Wr[KTOT * OUT_DIM];               // tf32-rounded We, [K, O] (32 MB)

// ---------------- helpers ----------------
__device__ __forceinline__ uint32_t f2tf32(float f) {
    uint32_t r;
    asm("cvt.rna.tf32.f32 %0, %1;" : "=r"(r) : "f"(f));
    return r;
}
__device__ __forceinline__ uint32_t smem_u32(const void* p) {
    uint32_t a;
    asm("{ .reg .u64 t; cvta.to.shared.u64 t, %1; cvt.u32.u64 %0, t; }" : "=r"(a) : "l"(p));
    return a;
}

// ---------------- kernel 1: gating softmax ----------------
__global__ __launch_bounds__(256) void gate_kernel(const float* __restrict__ x,
                                                   const float* __restrict__ Wg,
                                                   const float* __restrict__ bg) {
    __shared__ float sW[NE * IN_DIM];   // transposed: sW[e*1024 + i]
    int tid = threadIdx.x;
    for (int idx = tid; idx < NE * IN_DIM; idx += 256) {
        int i = idx >> 3, e = idx & 7;
        sW[e * IN_DIM + i] = Wg[idx];
    }
    __syncthreads();
    int w = tid >> 5, lane = tid & 31;
    int n = blockIdx.x * 8 + w;
    float acc[NE];
#pragma unroll
    for (int e = 0; e < NE; e++) acc[e] = 0.f;
    const float* xr = x + (size_t)n * IN_DIM;
    for (int i = lane; i < IN_DIM; i += 32) {
        float xv = xr[i];
#pragma unroll
        for (int e = 0; e < NE; e++) acc[e] += xv * sW[e * IN_DIM + i];
    }
#pragma unroll
    for (int e = 0; e < NE; e++) {
#pragma unroll
        for (int off = 16; off; off >>= 1)
            acc[e] += __shfl_xor_sync(0xffffffffu, acc[e], off);
    }
    if (lane == 0) {
        float v[NE], m = -1e30f;
#pragma unroll
        for (int e = 0; e < NE; e++) { v[e] = acc[e] + bg[e]; m = fmaxf(m, v[e]); }
        float s = 0.f;
#pragma unroll
        for (int e = 0; e < NE; e++) { v[e] = expf(v[e] - m); s += v[e]; }
        float inv = 1.0f / s;
#pragma unroll
        for (int e = 0; e < NE; e++) g_gates[n * NE + e] = v[e] * inv;
    }
}

// ---------------- kernel 2: tf32-round We (keeps [K, O] layout) ----------------
__global__ __launch_bounds__(256) void round_kernel(const float* __restrict__ We) {
    const float4* src = (const float4*)We;
    float4* dst = (float4*)g_Wr;
    int n = KTOT * OUT_DIM / 4;
    for (int idx = blockIdx.x * blockDim.x + threadIdx.x; idx < n;
         idx += gridDim.x * blockDim.x) {
        float4 v = src[idx];
        dst[idx] = make_float4(__uint_as_float(f2tf32(v.x)), __uint_as_float(f2tf32(v.y)),
                               __uint_as_float(f2tf32(v.z)), __uint_as_float(f2tf32(v.w)));
    }
}

// ---------------- kernel 3: fused tf32 mma.sync GEMM (bias folded into K) ----------------
__global__ __launch_bounds__(256) void moe_mma_kernel(const float* __restrict__ x,
                                                      const float* __restrict__ be,
                                                      float* __restrict__ out) {
    extern __shared__ __align__(16) float smem[];
    float* sA = smem;                                       // STAGES * SA_STAGE
    float* sB = smem + STAGES * SA_STAGE;                   // STAGES * SB_STAGE
    float* sg = smem + STAGES * SA_STAGE + STAGES * SB_STAGE;

    int tid = threadIdx.x;
    int m0 = blockIdx.y * BM, o0 = blockIdx.x * BN;

    for (int i = tid; i < BM * NE; i += 256) sg[i] = g_gates[m0 * NE + i];
    __syncthreads();

    // producer mappings
    const int row = tid >> 1, half = tid & 1;     // A: 2 threads per row, 8 floats each
    const int brow = tid >> 4, bseg = tid & 15;   // B: 16 threads per k-row, 2 x 16B each
    uint32_t aoff0 = smem_u32(sA) + (uint32_t)(row * SA_STRIDE + half * 8) * 4u;
    uint32_t boff0 = smem_u32(sB) + (uint32_t)(brow * SB_STRIDE + bseg * 4) * 4u;
    const uint32_t aStage = SA_STAGE * 4u;
    const uint32_t bStage = SB_STAGE * 4u;
    const float* xrow = x + (size_t)(m0 + row) * IN_DIM + half * 8;
    const float ge_bias0 = sg[row * NE + 0], ge_bias1 = sg[row * NE + 1];

    auto produceB = [&](int st, int c) {
        uint32_t d0 = boff0 + st * bStage;
        uint32_t d1 = d0 + 256;                    // +64 floats
        if (c < 512) {
            int ic = c >> 3, e = c & 7;
            const float* s0 = g_Wr + (size_t)(e * IN_DIM + ic * 16 + brow) * OUT_DIM + o0 + bseg * 4;
            asm volatile("cp.async.cg.shared.global [%0], [%1], 16;" :: "r"(d0), "l"(s0));
            asm volatile("cp.async.cg.shared.global [%0], [%1], 16;" :: "r"(d1), "l"(s0 + 64));
        } else {
            if (brow < 8) {
                const float* s0 = be + (size_t)brow * OUT_DIM + o0 + bseg * 4;
                asm volatile("cp.async.cg.shared.global [%0], [%1], 16;" :: "r"(d0), "l"(s0));
                asm volatile("cp.async.cg.shared.global [%0], [%1], 16;" :: "r"(d1), "l"(s0 + 64));
            } else {
                float4 z = make_float4(0.f, 0.f, 0.f, 0.f);
                *(float4*)&sB[st * SB_STAGE + brow * SB_STRIDE + bseg * 4] = z;
                *(float4*)&sB[st * SB_STAGE + brow * SB_STRIDE + bseg * 4 + 64] = z;
            }
        }
        asm volatile("cp.async.commit_group;");
    };
    auto st4tf = [&](uint32_t addr, float a, float b, float c2, float d) {
        asm volatile("st.shared.v4.b32 [%0], {%1,%2,%3,%4};"
                     :: "r"(addr), "r"(f2tf32(a)), "r"(f2tf32(b)), "r"(f2tf32(c2)), "r"(f2tf32(d)));
    };
    auto produceA = [&](int st, int c) {
        uint32_t dst = aoff0 + st * aStage;
        if (c < 512) {
            int ic = c >> 3, e = c & 7;
            float ge = sg[row * NE + e];
            const float4 v0 = *(const float4*)(xrow + ic * 16);
            const float4 v1 = *(const float4*)(xrow + ic * 16 + 4);
            st4tf(dst,      v0.x * ge, v0.y * ge, v0.z * ge, v0.w * ge);
            st4tf(dst + 16, v1.x * ge, v1.y * ge, v1.z * ge, v1.w * ge);
        } else {
            if (half == 0) {
                const float* g = &sg[row * NE];
                st4tf(dst,      g[0], g[1], g[2], g[3]);
                st4tf(dst + 16, g[4], g[5], g[6], g[7]);
            } else {
                st4tf(dst, 0.f, 0.f, 0.f, 0.f);
                st4tf(dst + 16, 0.f, 0.f, 0.f, 0.f);
            }
        }
    };

    // ---- accumulators / warp mapping ----
    float acc[4][4][4];
#pragma unroll
    for (int mi = 0; mi < 4; mi++)
#pragma unroll
        for (int ni = 0; ni < 4; ni++)
#pragma unroll
            for (int q = 0; q < 4; q++) acc[mi][ni][q] = 0.f;

    int wid = tid >> 5, lane = tid & 31;
    int wm = (wid & 1) * 64, wn = (wid >> 1) * 32;
    int lr = lane >> 2, lc = lane & 3;

    auto compute = [&](int st) {
        const float* A = sA + st * SA_STAGE;
        const float* B = sB + st * SB_STAGE;
#pragma unroll
        for (int s = 0; s < 2; s++) {
            uint32_t af[4][4], bf[4][2];
#pragma unroll
            for (int mi = 0; mi < 4; mi++) {
                int r = wm + mi * 16 + lr;
                int cc = s * 8 + lc;
                af[mi][0] = __float_as_uint(A[r * SA_STRIDE + cc]);
                af[mi][1] = __float_as_uint(A[(r + 8) * SA_STRIDE + cc]);
                af[mi][2] = __float_as_uint(A[r * SA_STRIDE + cc + 4]);
                af[mi][3] = __float_as_uint(A[(r + 8) * SA_STRIDE + cc + 4]);
            }
#pragma unroll
            for (int ni = 0; ni < 4; ni++) {
                int n = wn + ni * 8 + lr;
                int k = s * 8 + lc;
                bf[ni][0] = __float_as_uint(B[k * SB_STRIDE + n]);
                bf[ni][1] = __float_as_uint(B[(k + 4) * SB_STRIDE + n]);
            }
#pragma unroll
            for (int mi = 0; mi < 4; mi++)
#pragma unroll
                for (int ni = 0; ni < 4; ni++)
                    asm volatile(
                        "mma.sync.aligned.m16n8k8.row.col.f32.tf32.tf32.f32 "
                        "{%0,%1,%2,%3}, {%4,%5,%6,%7}, {%8,%9}, {%0,%1,%2,%3};"
                        : "+f"(acc[mi][ni][0]), "+f"(acc[mi][ni][1]),
                          "+f"(acc[mi][ni][2]), "+f"(acc[mi][ni][3])
                        : "r"(af[mi][0]), "r"(af[mi][1]), "r"(af[mi][2]), "r"(af[mi][3]),
                          "r"(bf[ni][0]), "r"(bf[ni][1]));
        }
    };

    // ---- prologue: fill stages 0..2 ----
#pragma unroll
    for (int s = 0; s < STAGES - 1; s++) {
        produceA(s, s);
        produceB(s, s);
    }

    // ---- main loop: iterations 0..509 always produce chunk c+3 ----
#pragma unroll 1
    for (int c = 0; c < NCHUNK - STAGES + 1; c++) {         // 0..509
        asm volatile("cp.async.wait_group %0;" :: "n"(STAGES - 2) : "memory");
        __syncthreads();
        int s3 = (c + STAGES - 1) & (STAGES - 1);
        produceA(s3, c + STAGES - 1);
        produceB(s3, c + STAGES - 1);
        compute(c & (STAGES - 1));
    }
    // ---- tail: chunks 510, 511, 512 all resident ----
    asm volatile("cp.async.wait_group 0;" ::: "memory");
    __syncthreads();
    compute(510 & (STAGES - 1));
    compute(511 & (STAGES - 1));
    compute(512 & (STAGES - 1));
    (void)ge_bias0; (void)ge_bias1;

    // ---- epilogue: pure store (bias folded into GEMM) ----
#pragma unroll
    for (int mi = 0; mi < 4; mi++) {
        int r = m0 + wm + mi * 16 + lr;
#pragma unroll
        for (int ni = 0; ni < 4; ni++) {
            int cc = o0 + wn + ni * 8 + lc * 2;
            *(float2*)(out + (size_t)r * OUT_DIM + cc) =
                make_float2(acc[mi][ni][0], acc[mi][ni][1]);
            *(float2*)(out + (size_t)(r + 8) * OUT_DIM + cc) =
                make_float2(acc[mi][ni][2], acc[mi][ni][3]);
        }
    }
}

// ---------------- launch ----------------
extern "C" void kernel_launch(void* const* d_in, const int* in_sizes, int n_in,
                              void* d_out, int out_size) {
    const float* x  = (const float*)d_in[0];
    const float* We = (const float*)d_in[1];
    const float* be = (const float*)d_in[2];
    const float* Wg = (const float*)d_in[3];
    const float* bg = (const float*)d_in[4];
    float* out = (float*)d_out;

    cudaFuncSetAttribute(moe_mma_kernel, cudaFuncAttributeMaxDynamicSharedMemorySize, SMEM_BYTES);

    gate_kernel<<<NTOK / 8, 256>>>(x, Wg, bg);
    round_kernel<<<2048, 256>>>(We);
    moe_mma_kernel<<<dim3(OUT_DIM / BN, NTOK / BM), 256, SMEM_BYTES>>>(x, be, out);
}

// round 5
// speedup vs baseline: 2.2478x; 2.2478x over previous
#include <cuda_runtime.h>
#include <cuda_fp16.h>
#include <cstdint>
#include <math.h>

#define IN_DIM  1024
#define OUT_DIM 1024
#define NE      8
#define NTOK    8192
#define KTOT    (NE * IN_DIM)          // 8192
#define BM      128
#define BN      128
#define NCHUNK  513                     // 512 weight chunks (K=16) + 1 gate/bias chunk
#define STAGES  4

// SMEM per stage (bytes)
#define SA_STAGE 4096                   // 128 rows x 16 half (fragment-permuted)
#define SB_STAGE 4352                   // 8 k-pair rows x 136 half2 (stride-136)

// ---------------- scratch ----------------
__device__ float    g_gates[NTOK * NE];              // softmax gates [N, E]
__device__ uint32_t g_Wh[(KTOT / 2) * OUT_DIM];      // half2(W[k],W[k+1])[o], 16 MB

// ---------------- helpers ----------------
__device__ __forceinline__ uint32_t smem_u32(const void* p) {
    uint32_t a;
    asm("{ .reg .u64 t; cvta.to.shared.u64 t, %1; cvt.u32.u64 %0, t; }" : "=r"(a) : "l"(p));
    return a;
}
__device__ __forceinline__ uint32_t packh2(float lo, float hi) {
    uint32_t r;
    asm("cvt.rn.f16x2.f32 %0, %1, %2;" : "=r"(r) : "f"(hi), "f"(lo));
    return r;
}

// ---------------- kernel 1: gating softmax ----------------
__global__ __launch_bounds__(256) void gate_kernel(const float* __restrict__ x,
                                                   const float* __restrict__ Wg,
                                                   const float* __restrict__ bg) {
    __shared__ float sW[NE * IN_DIM];   // transposed: sW[e*1024 + i]
    int tid = threadIdx.x;
    for (int idx = tid; idx < NE * IN_DIM; idx += 256) {
        int i = idx >> 3, e = idx & 7;
        sW[e * IN_DIM + i] = Wg[idx];
    }
    __syncthreads();
    int w = tid >> 5, lane = tid & 31;
    int n = blockIdx.x * 8 + w;
    float acc[NE];
#pragma unroll
    for (int e = 0; e < NE; e++) acc[e] = 0.f;
    const float* xr = x + (size_t)n * IN_DIM;
    for (int i = lane; i < IN_DIM; i += 32) {
        float xv = xr[i];
#pragma unroll
        for (int e = 0; e < NE; e++) acc[e] += xv * sW[e * IN_DIM + i];
    }
#pragma unroll
    for (int e = 0; e < NE; e++) {
#pragma unroll
        for (int off = 16; off; off >>= 1)
            acc[e] += __shfl_xor_sync(0xffffffffu, acc[e], off);
    }
    if (lane == 0) {
        float v[NE], m = -1e30f;
#pragma unroll
        for (int e = 0; e < NE; e++) { v[e] = acc[e] + bg[e]; m = fmaxf(m, v[e]); }
        float s = 0.f;
#pragma unroll
        for (int e = 0; e < NE; e++) { v[e] = expf(v[e] - m); s += v[e]; }
        float inv = 1.0f / s;
#pragma unroll
        for (int e = 0; e < NE; e++) g_gates[n * NE + e] = v[e] * inv;
    }
}

// ---------------- kernel 2: convert We -> half2 k-pair layout ----------------
// g_Wh[kp * OUT_DIM + o] = half2(We[2kp][o], We[2kp+1][o])
__global__ __launch_bounds__(256) void convert_kernel(const float* __restrict__ We) {
    int total = (KTOT / 2) * (OUT_DIM / 4);              // 1M quad-jobs
    for (int idx = blockIdx.x * blockDim.x + threadIdx.x; idx < total;
         idx += gridDim.x * blockDim.x) {
        int kp = idx >> 8;                               // / (OUT_DIM/4)
        int o  = (idx & 255) * 4;
        float4 r0 = *(const float4*)(We + (size_t)(2 * kp) * OUT_DIM + o);
        float4 r1 = *(const float4*)(We + (size_t)(2 * kp + 1) * OUT_DIM + o);
        uint4 w;
        w.x = packh2(r0.x, r1.x);
        w.y = packh2(r0.y, r1.y);
        w.z = packh2(r0.z, r1.z);
        w.w = packh2(r0.w, r1.w);
        *(uint4*)(g_Wh + (size_t)kp * OUT_DIM + o) = w;
    }
}

// ---------------- kernel 3: fused fp16 mma.sync GEMM (bias folded into K) ----------------
__global__ __launch_bounds__(256) void moe_mma_kernel(const float* __restrict__ x,
                                                      const float* __restrict__ be,
                                                      float* __restrict__ out) {
    __shared__ __align__(16) char sAraw[STAGES * SA_STAGE];
    __shared__ __align__(16) char sBraw[STAGES * SB_STAGE];
    __shared__ float sg[BM * NE];

    int tid = threadIdx.x;
    int m0 = blockIdx.y * BM, o0 = blockIdx.x * BN;

    for (int i = tid; i < BM * NE; i += 256) sg[i] = g_gates[m0 * NE + i];
    __syncthreads();

    // ---- producer mappings ----
    const int row = tid >> 1, half = tid & 1;   // A: 2 threads/row, 16B each
    const int kp = tid >> 5, seg = tid & 31;    // B: 32 threads per k-pair row, 16B each
    const uint32_t aBase = smem_u32(sAraw);
    const uint32_t bBase = smem_u32(sBraw);
    uint32_t aoff0 = aBase + (uint32_t)(row * 32 + half * 16);
    uint32_t boff0 = bBase + (uint32_t)(kp * 544 + seg * 16);
    const float* xrow = x + (size_t)(m0 + row) * IN_DIM + half * 4;

    auto produceB = [&](int st, int c) {
        uint32_t dst = boff0 + (uint32_t)st * SB_STAGE;
        if (c < 512) {
            int ic = c >> 3, e = c & 7;
            const uint32_t* src = g_Wh + (size_t)(e * 512 + ic * 8 + kp) * OUT_DIM + o0 + seg * 4;
            asm volatile("cp.async.cg.shared.global [%0], [%1], 16;" :: "r"(dst), "l"(src));
        } else {
            if (kp < 4) {
                float4 b0 = *(const float4*)(be + (size_t)(2 * kp) * OUT_DIM + o0 + seg * 4);
                float4 b1 = *(const float4*)(be + (size_t)(2 * kp + 1) * OUT_DIM + o0 + seg * 4);
                asm volatile("st.shared.v4.b32 [%0], {%1,%2,%3,%4};" :: "r"(dst),
                             "r"(packh2(b0.x, b1.x)), "r"(packh2(b0.y, b1.y)),
                             "r"(packh2(b0.z, b1.z)), "r"(packh2(b0.w, b1.w)));
            } else {
                asm volatile("st.shared.v4.b32 [%0], {%1,%1,%1,%1};" :: "r"(dst), "r"(0u));
            }
        }
        asm volatile("cp.async.commit_group;");
    };
    // A fragment-permuted row layout (half2 units): [u0,u4,u1,u5 | u2,u6,u3,u7]
    auto produceA = [&](int st, int c) {
        uint32_t dst = aoff0 + (uint32_t)st * SA_STAGE;
        if (c < 512) {
            int ic = c >> 3, e = c & 7;
            float ge = sg[row * NE + e];
            float4 v0 = *(const float4*)(xrow + ic * 16);       // cols h*4 .. h*4+3
            float4 v1 = *(const float4*)(xrow + ic * 16 + 8);   // cols h*4+8 .. +11
            asm volatile("st.shared.v4.b32 [%0], {%1,%2,%3,%4};" :: "r"(dst),
                         "r"(packh2(v0.x * ge, v0.y * ge)), "r"(packh2(v1.x * ge, v1.y * ge)),
                         "r"(packh2(v0.z * ge, v0.w * ge)), "r"(packh2(v1.z * ge, v1.w * ge)));
        } else {
            const float* g = &sg[row * NE + half * 4];
            asm volatile("st.shared.v4.b32 [%0], {%1,%2,%3,%4};" :: "r"(dst),
                         "r"(packh2(g[0], g[1])), "r"(0u), "r"(packh2(g[2], g[3])), "r"(0u));
        }
    };

    // ---- accumulators / warp mapping ----
    float acc[4][4][4];
#pragma unroll
    for (int mi = 0; mi < 4; mi++)
#pragma unroll
        for (int ni = 0; ni < 4; ni++)
#pragma unroll
            for (int q = 0; q < 4; q++) acc[mi][ni][q] = 0.f;

    int wid = tid >> 5, lane = tid & 31;
    int wm = (wid & 1) * 64, wn = (wid >> 1) * 32;
    int lr = lane >> 2, lc = lane & 3;

    auto compute = [&](int st) {
        const uint32_t A = aBase + (uint32_t)st * SA_STAGE;
        const uint32_t B = bBase + (uint32_t)st * SB_STAGE;
        uint32_t bf[4][2];
#pragma unroll
        for (int ni = 0; ni < 4; ni++) {
            int n = wn + ni * 8 + lr;
            asm volatile("ld.shared.b32 %0, [%1];" : "=r"(bf[ni][0]) : "r"(B + (uint32_t)((lc * 136 + n) * 4)));
            asm volatile("ld.shared.b32 %0, [%1];" : "=r"(bf[ni][1]) : "r"(B + (uint32_t)(((lc + 4) * 136 + n) * 4)));
        }
#pragma unroll
        for (int mi = 0; mi < 4; mi++) {
            int r = wm + mi * 16 + lr;
            uint32_t a0, a2, a1, a3;
            asm volatile("ld.shared.v2.b32 {%0,%1}, [%2];" : "=r"(a0), "=r"(a2)
                         : "r"(A + (uint32_t)(r * 32 + lc * 8)));
            asm volatile("ld.shared.v2.b32 {%0,%1}, [%2];" : "=r"(a1), "=r"(a3)
                         : "r"(A + (uint32_t)((r + 8) * 32 + lc * 8)));
#pragma unroll
            for (int ni = 0; ni < 4; ni++)
                asm volatile(
                    "mma.sync.aligned.m16n8k16.row.col.f32.f16.f16.f32 "
                    "{%0,%1,%2,%3}, {%4,%5,%6,%7}, {%8,%9}, {%0,%1,%2,%3};"
                    : "+f"(acc[mi][ni][0]), "+f"(acc[mi][ni][1]),
                      "+f"(acc[mi][ni][2]), "+f"(acc[mi][ni][3])
                    : "r"(a0), "r"(a1), "r"(a2), "r"(a3),
                      "r"(bf[ni][0]), "r"(bf[ni][1]));
        }
    };

    // ---- prologue: fill stages 0..2 ----
#pragma unroll
    for (int s = 0; s < STAGES - 1; s++) {
        produceA(s, s);
        produceB(s, s);
    }

    // ---- main loop ----
#pragma unroll 1
    for (int c = 0; c < NCHUNK - STAGES + 1; c++) {          // 0..509
        asm volatile("cp.async.wait_group %0;" :: "n"(STAGES - 2) : "memory");
        __syncthreads();
        int s3 = (c + STAGES - 1) & (STAGES - 1);
        produceA(s3, c + STAGES - 1);
        produceB(s3, c + STAGES - 1);
        compute(c & (STAGES - 1));
    }
    // ---- tail: chunks 510, 511, 512 resident ----
    asm volatile("cp.async.wait_group 0;" ::: "memory");
    __syncthreads();
    compute(510 & (STAGES - 1));
    compute(511 & (STAGES - 1));
    compute(512 & (STAGES - 1));

    // ---- epilogue: pure store (bias folded into GEMM) ----
#pragma unroll
    for (int mi = 0; mi < 4; mi++) {
        int r = m0 + wm + mi * 16 + lr;
#pragma unroll
        for (int ni = 0; ni < 4; ni++) {
            int cc = o0 + wn + ni * 8 + lc * 2;
            *(float2*)(out + (size_t)r * OUT_DIM + cc) =
                make_float2(acc[mi][ni][0], acc[mi][ni][1]);
            *(float2*)(out + (size_t)(r + 8) * OUT_DIM + cc) =
                make_float2(acc[mi][ni][2], acc[mi][ni][3]);
        }
    }
}

// ---------------- launch ----------------
extern "C" void kernel_launch(void* const* d_in, const int* in_sizes, int n_in,
                              void* d_out, int out_size) {
    const float* x  = (const float*)d_in[0];
    const float* We = (const float*)d_in[1];
    const float* be = (const float*)d_in[2];
    const float* Wg = (const float*)d_in[3];
    const float* bg = (const float*)d_in[4];
    float* out = (float*)d_out;

    gate_kernel<<<NTOK / 8, 256>>>(x, Wg, bg);
    convert_kernel<<<2048, 256>>>(We);
    moe_mma_kernel<<<dim3(OUT_DIM / BN, NTOK / BM), 256>>>(x, be, out);
}

// round 6
// speedup vs baseline: 2.2815x; 1.0150x over previous
#include <cuda_runtime.h>
#include <cuda_fp16.h>
#include <cstdint>
#include <math.h>

#define IN_DIM  1024
#define OUT_DIM 1024
#define NE      8
#define NTOK    8192
#define KTOT    (NE * IN_DIM)          // 8192
#define BM      128
#define BN      128
#define NCHUNK  257                     // 256 weight chunks (K=32) + 1 gate/bias chunk
#define STAGES  3

// SMEM per stage (bytes)
#define SA_STAGE 8192                   // 128 rows x 32 half (2 fragment-permuted k16 groups)
#define SB_STAGE 8704                   // 16 kp rows x 136 half2 (stride-136)
#define SB_BASE  (STAGES * SA_STAGE)                     // 24576
#define SG_BASE  (SB_BASE + STAGES * SB_STAGE)           // 50688
#define SMEM_BYTES (SG_BASE + BM * NE * 4)               // 54784

// ---------------- scratch ----------------
__device__ float    g_gates[NTOK * NE];              // softmax gates [N, E]
__device__ uint32_t g_Wh[(KTOT / 2) * OUT_DIM];      // half2(W[k],W[k+1])[o], 16 MB

// ---------------- helpers ----------------
__device__ __forceinline__ uint32_t smem_u32(const void* p) {
    uint32_t a;
    asm("{ .reg .u64 t; cvta.to.shared.u64 t, %1; cvt.u32.u64 %0, t; }" : "=r"(a) : "l"(p));
    return a;
}
__device__ __forceinline__ uint32_t packh2(float lo, float hi) {
    uint32_t r;
    asm("cvt.rn.f16x2.f32 %0, %1, %2;" : "=r"(r) : "f"(hi), "f"(lo));
    return r;
}

// ---------------- kernel 1: gating softmax ----------------
__global__ __launch_bounds__(256) void gate_kernel(const float* __restrict__ x,
                                                   const float* __restrict__ Wg,
                                                   const float* __restrict__ bg) {
    __shared__ float sW[NE * IN_DIM];   // transposed: sW[e*1024 + i]
    int tid = threadIdx.x;
    for (int idx = tid; idx < NE * IN_DIM; idx += 256) {
        int i = idx >> 3, e = idx & 7;
        sW[e * IN_DIM + i] = Wg[idx];
    }
    __syncthreads();
    int w = tid >> 5, lane = tid & 31;
    int n = blockIdx.x * 8 + w;
    float acc[NE];
#pragma unroll
    for (int e = 0; e < NE; e++) acc[e] = 0.f;
    const float* xr = x + (size_t)n * IN_DIM;
    for (int i = lane; i < IN_DIM; i += 32) {
        float xv = xr[i];
#pragma unroll
        for (int e = 0; e < NE; e++) acc[e] += xv * sW[e * IN_DIM + i];
    }
#pragma unroll
    for (int e = 0; e < NE; e++) {
#pragma unroll
        for (int off = 16; off; off >>= 1)
            acc[e] += __shfl_xor_sync(0xffffffffu, acc[e], off);
    }
    if (lane == 0) {
        float v[NE], m = -1e30f;
#pragma unroll
        for (int e = 0; e < NE; e++) { v[e] = acc[e] + bg[e]; m = fmaxf(m, v[e]); }
        float s = 0.f;
#pragma unroll
        for (int e = 0; e < NE; e++) { v[e] = expf(v[e] - m); s += v[e]; }
        float inv = 1.0f / s;
#pragma unroll
        for (int e = 0; e < NE; e++) g_gates[n * NE + e] = v[e] * inv;
    }
}

// ---------------- kernel 2: convert We -> half2 k-pair layout ----------------
__global__ __launch_bounds__(256) void convert_kernel(const float* __restrict__ We) {
    int total = (KTOT / 2) * (OUT_DIM / 4);
    for (int idx = blockIdx.x * blockDim.x + threadIdx.x; idx < total;
         idx += gridDim.x * blockDim.x) {
        int kp = idx >> 8;
        int o  = (idx & 255) * 4;
        float4 r0 = *(const float4*)(We + (size_t)(2 * kp) * OUT_DIM + o);
        float4 r1 = *(const float4*)(We + (size_t)(2 * kp + 1) * OUT_DIM + o);
        uint4 w;
        w.x = packh2(r0.x, r1.x);
        w.y = packh2(r0.y, r1.y);
        w.z = packh2(r0.z, r1.z);
        w.w = packh2(r0.w, r1.w);
        *(uint4*)(g_Wh + (size_t)kp * OUT_DIM + o) = w;
    }
}

// ---------------- kernel 3: fused fp16 mma.sync GEMM, K=32 chunks ----------------
__global__ __launch_bounds__(256, 2) void moe_mma_kernel(const float* __restrict__ x,
                                                         const float* __restrict__ be,
                                                         float* __restrict__ out) {
    extern __shared__ __align__(16) char smem[];
    const uint32_t aBase = smem_u32(smem);
    const uint32_t bBase = aBase + SB_BASE;
    float* sg = (float*)(smem + SG_BASE);

    int tid = threadIdx.x;
    int m0 = blockIdx.y * BM, o0 = blockIdx.x * BN;

    for (int i = tid; i < BM * NE; i += 256) sg[i] = g_gates[m0 * NE + i];
    __syncthreads();

    // ---- producer mappings ----
    const int row = tid >> 1, half = tid & 1;     // A: 2 threads/row
    const int kp = tid >> 4, seg = tid & 15;      // B: 16 threads per kp-row, 2 x 16B each
    uint32_t aoff0 = aBase + (uint32_t)(row * 64 + half * 16);
    uint32_t boff0 = bBase + (uint32_t)(kp * 544 + seg * 16);
    const float* xrow = x + (size_t)(m0 + row) * IN_DIM + half * 4;

    auto produceB = [&](int st, int c) {
        uint32_t d0 = boff0 + (uint32_t)st * SB_STAGE;
        uint32_t d1 = d0 + 256;                   // +64 half2
        if (c < 256) {
            int ic = c >> 3, e = c & 7;
            const uint32_t* src = g_Wh + (size_t)(e * 512 + ic * 16 + kp) * OUT_DIM + o0 + seg * 4;
            asm volatile("cp.async.cg.shared.global [%0], [%1], 16;" :: "r"(d0), "l"(src));
            asm volatile("cp.async.cg.shared.global [%0], [%1], 16;" :: "r"(d1), "l"(src + 64));
        } else {
            if (kp < 4) {
                const float* s0 = be + (size_t)(2 * kp) * OUT_DIM + o0 + seg * 4;
                const float* s1 = be + (size_t)(2 * kp + 1) * OUT_DIM + o0 + seg * 4;
                float4 b0 = *(const float4*)s0, b1 = *(const float4*)s1;
                asm volatile("st.shared.v4.b32 [%0], {%1,%2,%3,%4};" :: "r"(d0),
                             "r"(packh2(b0.x, b1.x)), "r"(packh2(b0.y, b1.y)),
                             "r"(packh2(b0.z, b1.z)), "r"(packh2(b0.w, b1.w)));
                b0 = *(const float4*)(s0 + 64); b1 = *(const float4*)(s1 + 64);
                asm volatile("st.shared.v4.b32 [%0], {%1,%2,%3,%4};" :: "r"(d1),
                             "r"(packh2(b0.x, b1.x)), "r"(packh2(b0.y, b1.y)),
                             "r"(packh2(b0.z, b1.z)), "r"(packh2(b0.w, b1.w)));
            } else {
                asm volatile("st.shared.v4.b32 [%0], {%1,%1,%1,%1};" :: "r"(d0), "r"(0u));
                asm volatile("st.shared.v4.b32 [%0], {%1,%1,%1,%1};" :: "r"(d1), "r"(0u));
            }
        }
        asm volatile("cp.async.commit_group;");
    };
    // A row layout per k16 group g (half2 units): [u0,u4,u1,u5 | u2,u6,u3,u7]
    auto produceA = [&](int st, int c) {
        uint32_t dst = aoff0 + (uint32_t)st * SA_STAGE;
        if (c < 256) {
            int ic = c >> 3, e = c & 7;
            float ge = sg[row * NE + e];
#pragma unroll
            for (int g = 0; g < 2; g++) {
                const float* p = xrow + ic * 32 + g * 16;
                float4 v0 = *(const float4*)(p);
                float4 v1 = *(const float4*)(p + 8);
                asm volatile("st.shared.v4.b32 [%0], {%1,%2,%3,%4};" :: "r"(dst + g * 32),
                             "r"(packh2(v0.x * ge, v0.y * ge)), "r"(packh2(v1.x * ge, v1.y * ge)),
                             "r"(packh2(v0.z * ge, v0.w * ge)), "r"(packh2(v1.z * ge, v1.w * ge)));
            }
        } else {
            const float* g = &sg[row * NE + half * 4];
            asm volatile("st.shared.v4.b32 [%0], {%1,%2,%3,%4};" :: "r"(dst),
                         "r"(packh2(g[0], g[1])), "r"(0u), "r"(packh2(g[2], g[3])), "r"(0u));
            asm volatile("st.shared.v4.b32 [%0], {%1,%1,%1,%1};" :: "r"(dst + 32), "r"(0u));
        }
    };

    // ---- accumulators / warp mapping ----
    float acc[4][4][4];
#pragma unroll
    for (int mi = 0; mi < 4; mi++)
#pragma unroll
        for (int ni = 0; ni < 4; ni++)
#pragma unroll
            for (int q = 0; q < 4; q++) acc[mi][ni][q] = 0.f;

    int wid = tid >> 5, lane = tid & 31;
    int wm = (wid & 1) * 64, wn = (wid >> 1) * 32;
    int lr = lane >> 2, lc = lane & 3;

    auto compute = [&](int st) {
        const uint32_t A = aBase + (uint32_t)st * SA_STAGE;
        const uint32_t B = bBase + (uint32_t)st * SB_STAGE;
#pragma unroll
        for (int ks = 0; ks < 2; ks++) {
            uint32_t bf[4][2];
#pragma unroll
            for (int ni = 0; ni < 4; ni++) {
                int n = wn + ni * 8 + lr;
                asm volatile("ld.shared.b32 %0, [%1];" : "=r"(bf[ni][0])
                             : "r"(B + (uint32_t)(((ks * 8 + lc) * 136 + n) * 4)));
                asm volatile("ld.shared.b32 %0, [%1];" : "=r"(bf[ni][1])
                             : "r"(B + (uint32_t)(((ks * 8 + lc + 4) * 136 + n) * 4)));
            }
#pragma unroll
            for (int mi = 0; mi < 4; mi++) {
                int r = wm + mi * 16 + lr;
                uint32_t a0, a2, a1, a3;
                asm volatile("ld.shared.v2.b32 {%0,%1}, [%2];" : "=r"(a0), "=r"(a2)
                             : "r"(A + (uint32_t)(r * 64 + ks * 32 + lc * 8)));
                asm volatile("ld.shared.v2.b32 {%0,%1}, [%2];" : "=r"(a1), "=r"(a3)
                             : "r"(A + (uint32_t)((r + 8) * 64 + ks * 32 + lc * 8)));
#pragma unroll
                for (int ni = 0; ni < 4; ni++)
                    asm volatile(
                        "mma.sync.aligned.m16n8k16.row.col.f32.f16.f16.f32 "
                        "{%0,%1,%2,%3}, {%4,%5,%6,%7}, {%8,%9}, {%0,%1,%2,%3};"
                        : "+f"(acc[mi][ni][0]), "+f"(acc[mi][ni][1]),
                          "+f"(acc[mi][ni][2]), "+f"(acc[mi][ni][3])
                        : "r"(a0), "r"(a1), "r"(a2), "r"(a3),
                          "r"(bf[ni][0]), "r"(bf[ni][1]));
            }
        }
    };

    // ---- prologue: fill stages 0, 1 ----
#pragma unroll
    for (int s = 0; s < STAGES - 1; s++) {
        produceA(s, s);
        produceB(s, s);
    }

    // ---- main loop: c = 0..254, produce chunk c+2 ----
    int st_c = 0, st_p = 2;
#pragma unroll 1
    for (int c = 0; c < NCHUNK - STAGES + 1; c++) {          // 0..254
        asm volatile("cp.async.wait_group %0;" :: "n"(STAGES - 2) : "memory");
        __syncthreads();
        produceA(st_p, c + 2);
        produceB(st_p, c + 2);
        compute(st_c);
        st_c = (st_c == 2) ? 0 : st_c + 1;
        st_p = (st_p == 2) ? 0 : st_p + 1;
    }
    // ---- tail: chunks 255, 256 resident (stages st_c, st_c+1) ----
    asm volatile("cp.async.wait_group 0;" ::: "memory");
    __syncthreads();
    compute(st_c);
    compute((st_c == 2) ? 0 : st_c + 1);

    // ---- epilogue: pure store (bias folded into GEMM) ----
#pragma unroll
    for (int mi = 0; mi < 4; mi++) {
        int r = m0 + wm + mi * 16 + lr;
#pragma unroll
        for (int ni = 0; ni < 4; ni++) {
            int cc = o0 + wn + ni * 8 + lc * 2;
            *(float2*)(out + (size_t)r * OUT_DIM + cc) =
                make_float2(acc[mi][ni][0], acc[mi][ni][1]);
            *(float2*)(out + (size_t)(r + 8) * OUT_DIM + cc) =
                make_float2(acc[mi][ni][2], acc[mi][ni][3]);
        }
    }
}

// ---------------- launch ----------------
extern "C" void kernel_launch(void* const* d_in, const int* in_sizes, int n_in,
                              void* d_out, int out_size) {
    const float* x  = (const float*)d_in[0];
    const float* We = (const float*)d_in[1];
    const float* be = (const float*)d_in[2];
    const float* Wg = (const float*)d_in[3];
    const float* bg = (const float*)d_in[4];
    float* out = (float*)d_out;

    cudaFuncSetAttribute(moe_mma_kernel, cudaFuncAttributeMaxDynamicSharedMemorySize, SMEM_BYTES);

    gate_kernel<<<NTOK / 8, 256>>>(x, Wg, bg);
    convert_kernel<<<2048, 256>>>(We);
    moe_mma_kernel<<<dim3(OUT_DIM / BN, NTOK / BM), 256, SMEM_BYTES>>>(x, be, out);
}

// round 7
// speedup vs baseline: 2.7318x; 1.1974x over previous
#include <cuda_runtime.h>
#include <cuda_fp16.h>
#include <cstdint>
#include <math.h>

#define IN_DIM  1024
#define OUT_DIM 1024
#define NE      8
#define NTOK    8192
#define KTOT    (NE * IN_DIM)          // 8192
#define BM      128
#define BN      128
#define NCHUNK  257                     // 256 weight chunks (K=32) + 1 gate/bias chunk
#define STAGES  3

// SMEM per stage (bytes)
// A: 16 m8-blocks x 4 k8-blocks x 128B (8x8 fp16 matrices, block-contiguous)
#define SA_STAGE 8192
#define SB_STAGE 8704                   // 16 kp rows x 136 half2 (stride-136)
#define SB_BASE  (STAGES * SA_STAGE)                     // 24576
#define SG_BASE  (SB_BASE + STAGES * SB_STAGE)           // 50688
#define SMEM_BYTES (SG_BASE + BM * NE * 4)               // 54784

// ---------------- scratch ----------------
__device__ float    g_gates[NTOK * NE];              // softmax gates [N, E]
__device__ uint32_t g_Wh[(KTOT / 2) * OUT_DIM];      // half2(W[k],W[k+1])[o], 16 MB

// ---------------- helpers ----------------
__device__ __forceinline__ uint32_t smem_u32(const void* p) {
    uint32_t a;
    asm("{ .reg .u64 t; cvta.to.shared.u64 t, %1; cvt.u32.u64 %0, t; }" : "=r"(a) : "l"(p));
    return a;
}
__device__ __forceinline__ uint32_t packh2(float lo, float hi) {
    uint32_t r;
    asm("cvt.rn.f16x2.f32 %0, %1, %2;" : "=r"(r) : "f"(hi), "f"(lo));
    return r;
}

// ---------------- kernel 1: gating softmax ----------------
__global__ __launch_bounds__(256) void gate_kernel(const float* __restrict__ x,
                                                   const float* __restrict__ Wg,
                                                   const float* __restrict__ bg) {
    __shared__ float sW[NE * IN_DIM];   // transposed: sW[e*1024 + i]
    int tid = threadIdx.x;
    for (int idx = tid; idx < NE * IN_DIM; idx += 256) {
        int i = idx >> 3, e = idx & 7;
        sW[e * IN_DIM + i] = Wg[idx];
    }
    __syncthreads();
    int w = tid >> 5, lane = tid & 31;
    int n = blockIdx.x * 8 + w;
    float acc[NE];
#pragma unroll
    for (int e = 0; e < NE; e++) acc[e] = 0.f;
    const float* xr = x + (size_t)n * IN_DIM;
    for (int i = lane; i < IN_DIM; i += 32) {
        float xv = xr[i];
#pragma unroll
        for (int e = 0; e < NE; e++) acc[e] += xv * sW[e * IN_DIM + i];
    }
#pragma unroll
    for (int e = 0; e < NE; e++) {
#pragma unroll
        for (int off = 16; off; off >>= 1)
            acc[e] += __shfl_xor_sync(0xffffffffu, acc[e], off);
    }
    if (lane == 0) {
        float v[NE], m = -1e30f;
#pragma unroll
        for (int e = 0; e < NE; e++) { v[e] = acc[e] + bg[e]; m = fmaxf(m, v[e]); }
        float s = 0.f;
#pragma unroll
        for (int e = 0; e < NE; e++) { v[e] = expf(v[e] - m); s += v[e]; }
        float inv = 1.0f / s;
#pragma unroll
        for (int e = 0; e < NE; e++) g_gates[n * NE + e] = v[e] * inv;
    }
}

// ---------------- kernel 2: convert We -> half2 k-pair layout ----------------
__global__ __launch_bounds__(256) void convert_kernel(const float* __restrict__ We) {
    int total = (KTOT / 2) * (OUT_DIM / 4);
    for (int idx = blockIdx.x * blockDim.x + threadIdx.x; idx < total;
         idx += gridDim.x * blockDim.x) {
        int kp = idx >> 8;
        int o  = (idx & 255) * 4;
        float4 r0 = *(const float4*)(We + (size_t)(2 * kp) * OUT_DIM + o);
        float4 r1 = *(const float4*)(We + (size_t)(2 * kp + 1) * OUT_DIM + o);
        uint4 w;
        w.x = packh2(r0.x, r1.x);
        w.y = packh2(r0.y, r1.y);
        w.z = packh2(r0.z, r1.z);
        w.w = packh2(r0.w, r1.w);
        *(uint4*)(g_Wh + (size_t)kp * OUT_DIM + o) = w;
    }
}

// ---------------- kernel 3: fused fp16 mma.sync GEMM, ldmatrix A path ----------------
// A block layout: block(m8 in 0..15, k8 in 0..3) at offset (m8*4+k8)*128,
// row r8 stored at swizzled slot ((r8 + 4*k8) & 7) * 16 within the block.
__global__ __launch_bounds__(256, 2) void moe_mma_kernel(const float* __restrict__ x,
                                                         const float* __restrict__ be,
                                                         float* __restrict__ out) {
    extern __shared__ __align__(16) char smem[];
    const uint32_t aBase = smem_u32(smem);
    const uint32_t bBase = aBase + SB_BASE;
    float* sg = (float*)(smem + SG_BASE);

    int tid = threadIdx.x;
    int m0 = blockIdx.y * BM, o0 = blockIdx.x * BN;

    for (int i = tid; i < BM * NE; i += 256) sg[i] = g_gates[m0 * NE + i];
    __syncthreads();

    // ---- producer mappings ----
    const int row = tid >> 1, h = tid & 1;        // A: 2 threads/row, k8 in {h, h+2}
    const int kp = tid >> 4, seg = tid & 15;      // B: 16 threads per kp-row, 2 x 16B each
    const int m8p = row >> 3, r8p = row & 7;
    // A producer STS addresses for k8 = h and h + 2 (lane-constant)
    const uint32_t aoffQ0 = (uint32_t)(((m8p * 4 + h) * 128) + (((r8p + 4 * h) & 7) * 16));
    const uint32_t aoffQ1 = (uint32_t)(((m8p * 4 + h + 2) * 128) + (((r8p + 4 * (h + 2)) & 7) * 16));
    uint32_t boff0 = bBase + (uint32_t)(kp * 544 + seg * 16);
    const float* xrow = x + (size_t)(m0 + row) * IN_DIM;

    auto produceB = [&](int st, int c) {
        uint32_t d0 = boff0 + (uint32_t)st * SB_STAGE;
        uint32_t d1 = d0 + 256;                   // +64 half2
        if (c < 256) {
            int ic = c >> 3, e = c & 7;
            const uint32_t* src = g_Wh + (size_t)(e * 512 + ic * 16 + kp) * OUT_DIM + o0 + seg * 4;
            asm volatile("cp.async.cg.shared.global [%0], [%1], 16;" :: "r"(d0), "l"(src));
            asm volatile("cp.async.cg.shared.global [%0], [%1], 16;" :: "r"(d1), "l"(src + 64));
        } else {
            if (kp < 4) {
                const float* s0 = be + (size_t)(2 * kp) * OUT_DIM + o0 + seg * 4;
                const float* s1 = be + (size_t)(2 * kp + 1) * OUT_DIM + o0 + seg * 4;
                float4 b0 = *(const float4*)s0, b1 = *(const float4*)s1;
                asm volatile("st.shared.v4.b32 [%0], {%1,%2,%3,%4};" :: "r"(d0),
                             "r"(packh2(b0.x, b1.x)), "r"(packh2(b0.y, b1.y)),
                             "r"(packh2(b0.z, b1.z)), "r"(packh2(b0.w, b1.w)));
                b0 = *(const float4*)(s0 + 64); b1 = *(const float4*)(s1 + 64);
                asm volatile("st.shared.v4.b32 [%0], {%1,%2,%3,%4};" :: "r"(d1),
                             "r"(packh2(b0.x, b1.x)), "r"(packh2(b0.y, b1.y)),
                             "r"(packh2(b0.z, b1.z)), "r"(packh2(b0.w, b1.w)));
            } else {
                asm volatile("st.shared.v4.b32 [%0], {%1,%1,%1,%1};" :: "r"(d0), "r"(0u));
                asm volatile("st.shared.v4.b32 [%0], {%1,%1,%1,%1};" :: "r"(d1), "r"(0u));
            }
        }
        asm volatile("cp.async.commit_group;");
    };
    auto produceA = [&](int st, int c) {
        uint32_t base = aBase + (uint32_t)st * SA_STAGE;
        if (c < 256) {
            int ic = c >> 3, e = c & 7;
            float ge = sg[row * NE + e];
            {   // quad k8 = h : k in [8h, 8h+8)
                const float* p = xrow + ic * 32 + h * 8;
                float4 v0 = *(const float4*)p, v1 = *(const float4*)(p + 4);
                asm volatile("st.shared.v4.b32 [%0], {%1,%2,%3,%4};" :: "r"(base + aoffQ0),
                             "r"(packh2(v0.x * ge, v0.y * ge)), "r"(packh2(v0.z * ge, v0.w * ge)),
                             "r"(packh2(v1.x * ge, v1.y * ge)), "r"(packh2(v1.z * ge, v1.w * ge)));
            }
            {   // quad k8 = h+2 : k in [16+8h, 16+8h+8)
                const float* p = xrow + ic * 32 + 16 + h * 8;
                float4 v0 = *(const float4*)p, v1 = *(const float4*)(p + 4);
                asm volatile("st.shared.v4.b32 [%0], {%1,%2,%3,%4};" :: "r"(base + aoffQ1),
                             "r"(packh2(v0.x * ge, v0.y * ge)), "r"(packh2(v0.z * ge, v0.w * ge)),
                             "r"(packh2(v1.x * ge, v1.y * ge)), "r"(packh2(v1.z * ge, v1.w * ge)));
            }
        } else {
            // bias chunk: A[row, k] = gates[row][k] for k<8, else 0  (k8==0 holds gates)
            if (h == 0) {
                const float* g = &sg[row * NE];
                asm volatile("st.shared.v4.b32 [%0], {%1,%2,%3,%4};" :: "r"(base + aoffQ0),
                             "r"(packh2(g[0], g[1])), "r"(packh2(g[2], g[3])),
                             "r"(packh2(g[4], g[5])), "r"(packh2(g[6], g[7])));
            } else {
                asm volatile("st.shared.v4.b32 [%0], {%1,%1,%1,%1};" :: "r"(base + aoffQ0), "r"(0u));
            }
            asm volatile("st.shared.v4.b32 [%0], {%1,%1,%1,%1};" :: "r"(base + aoffQ1), "r"(0u));
        }
    };

    // ---- accumulators / warp mapping ----
    float acc[4][4][4];
#pragma unroll
    for (int mi = 0; mi < 4; mi++)
#pragma unroll
        for (int ni = 0; ni < 4; ni++)
#pragma unroll
            for (int q = 0; q < 4; q++) acc[mi][ni][q] = 0.f;

    int wid = tid >> 5, lane = tid & 31;
    int wm = (wid & 1) * 64, wn = (wid >> 1) * 32;
    int lr = lane >> 2, lc = lane & 3;
    const int wmBlk = (wid & 1) * 8;              // m8 base for this warp

    // ldmatrix per-lane constant: matrix j = lane>>3, rr = lane&7
    // block += (j&1)*4 + (j>>1); swizzled row = (rr + 4*(j>>1)) & 7
    const int jm = (lane >> 3) & 1, jk = lane >> 4, rr = lane & 7;
    const uint32_t aLane = (uint32_t)((jm * 4 + jk) * 128 + (((rr + 4 * jk) & 7) * 16));

    auto compute = [&](int st) {
        const uint32_t A = aBase + (uint32_t)st * SA_STAGE + aLane;
        const uint32_t B = bBase + (uint32_t)st * SB_STAGE;
#pragma unroll
        for (int ks = 0; ks < 2; ks++) {
            uint32_t bf[4][2];
#pragma unroll
            for (int ni = 0; ni < 4; ni++) {
                int n = wn + ni * 8 + lr;
                asm volatile("ld.shared.b32 %0, [%1];" : "=r"(bf[ni][0])
                             : "r"(B + (uint32_t)(((ks * 8 + lc) * 136 + n) * 4)));
                asm volatile("ld.shared.b32 %0, [%1];" : "=r"(bf[ni][1])
                             : "r"(B + (uint32_t)(((ks * 8 + lc + 4) * 136 + n) * 4)));
            }
#pragma unroll
            for (int mi = 0; mi < 4; mi++) {
                uint32_t a0, a1, a2, a3;
                uint32_t addr = A + (uint32_t)((((wmBlk + 2 * mi) * 4) + 2 * ks) * 128);
                asm volatile("ldmatrix.sync.aligned.m8n8.x4.shared.b16 {%0,%1,%2,%3}, [%4];"
                             : "=r"(a0), "=r"(a1), "=r"(a2), "=r"(a3) : "r"(addr));
#pragma unroll
                for (int ni = 0; ni < 4; ni++)
                    asm volatile(
                        "mma.sync.aligned.m16n8k16.row.col.f32.f16.f16.f32 "
                        "{%0,%1,%2,%3}, {%4,%5,%6,%7}, {%8,%9}, {%0,%1,%2,%3};"
                        : "+f"(acc[mi][ni][0]), "+f"(acc[mi][ni][1]),
                          "+f"(acc[mi][ni][2]), "+f"(acc[mi][ni][3])
                        : "r"(a0), "r"(a1), "r"(a2), "r"(a3),
                          "r"(bf[ni][0]), "r"(bf[ni][1]));
            }
        }
    };

    // ---- prologue: fill stages 0, 1 ----
#pragma unroll
    for (int s = 0; s < STAGES - 1; s++) {
        produceA(s, s);
        produceB(s, s);
    }

    // ---- main loop: c = 0..254, produce chunk c+2 ----
    int st_c = 0, st_p = 2;
#pragma unroll 1
    for (int c = 0; c < NCHUNK - STAGES + 1; c++) {          // 0..254
        asm volatile("cp.async.wait_group %0;" :: "n"(STAGES - 2) : "memory");
        __syncthreads();
        produceA(st_p, c + 2);
        produceB(st_p, c + 2);
        compute(st_c);
        st_c = (st_c == 2) ? 0 : st_c + 1;
        st_p = (st_p == 2) ? 0 : st_p + 1;
    }
    // ---- tail: chunks 255, 256 resident ----
    asm volatile("cp.async.wait_group 0;" ::: "memory");
    __syncthreads();
    compute(st_c);
    compute((st_c == 2) ? 0 : st_c + 1);

    // ---- epilogue: pure store (bias folded into GEMM) ----
#pragma unroll
    for (int mi = 0; mi < 4; mi++) {
        int r = m0 + wm + mi * 16 + lr;
#pragma unroll
        for (int ni = 0; ni < 4; ni++) {
            int cc = o0 + wn + ni * 8 + lc * 2;
            *(float2*)(out + (size_t)r * OUT_DIM + cc) =
                make_float2(acc[mi][ni][0], acc[mi][ni][1]);
            *(float2*)(out + (size_t)(r + 8) * OUT_DIM + cc) =
                make_float2(acc[mi][ni][2], acc[mi][ni][3]);
        }
    }
}

// ---------------- launch ----------------
extern "C" void kernel_launch(void* const* d_in, const int* in_sizes, int n_in,
                              void* d_out, int out_size) {
    const float* x  = (const float*)d_in[0];
    const float* We = (const float*)d_in[1];
    const float* be = (const float*)d_in[2];
    const float* Wg = (const float*)d_in[3];
    const float* bg = (const float*)d_in[4];
    float* out = (float*)d_out;

    cudaFuncSetAttribute(moe_mma_kernel, cudaFuncAttributeMaxDynamicSharedMemorySize, SMEM_BYTES);

    gate_kernel<<<NTOK / 8, 256>>>(x, Wg, bg);
    convert_kernel<<<2048, 256>>>(We);
    moe_mma_kernel<<<dim3(OUT_DIM / BN, NTOK / BM), 256, SMEM_BYTES>>>(x, be, out);
}

// round 8
// speedup vs baseline: 2.8730x; 1.0517x over previous
#include <cuda_runtime.h>
#include <cuda_fp16.h>
#include <cstdint>
#include <math.h>

#define IN_DIM  1024
#define OUT_DIM 1024
#define NE      8
#define NTOK    8192
#define KTOT    (NE * IN_DIM)          // 8192
#define BM      128
#define BN      128
#define NCHUNK  257                     // 256 weight chunks (K=32) + 1 gate/bias chunk
#define STAGES  4

// SMEM per stage (bytes)
#define SA_STAGE 8192                   // A: 16 m8-blocks x 4 k8-blocks x 128B
#define SB_STAGE 8192                   // B: 32 k-rows x 256B (swizzled 16B cols)
#define SB_BASE  (STAGES * SA_STAGE)                     // 32768
#define SG_BASE  (SB_BASE + STAGES * SB_STAGE)           // 65536
#define SMEM_BYTES (SG_BASE + BM * NE * 4)               // 69632

// ---------------- scratch ----------------
__device__ float  g_gates[NTOK * NE];                // softmax gates [N, E]
__device__ __half g_Wh[KTOT * OUT_DIM];              // fp16 We, [K, O] row-major, 16 MB

// ---------------- helpers ----------------
__device__ __forceinline__ uint32_t smem_u32(const void* p) {
    uint32_t a;
    asm("{ .reg .u64 t; cvta.to.shared.u64 t, %1; cvt.u32.u64 %0, t; }" : "=r"(a) : "l"(p));
    return a;
}
__device__ __forceinline__ uint32_t packh2(float lo, float hi) {
    uint32_t r;
    asm("cvt.rn.f16x2.f32 %0, %1, %2;" : "=r"(r) : "f"(hi), "f"(lo));
    return r;
}
// swizzled byte offset of 16B col-slot `col16` in k-row `kr` of a B stage
__device__ __forceinline__ uint32_t bswz(int kr, int col16) {
    return (uint32_t)(kr * 256 + ((((col16 ^ kr) & 7) | (col16 & 8)) << 4));
}

// ---------------- kernel 1: gating softmax (32 tokens / 1024-thread block) ----------------
__global__ __launch_bounds__(1024) void gate_kernel(const float* __restrict__ x,
                                                    const float* __restrict__ Wg,
                                                    const float* __restrict__ bg) {
    __shared__ float sW[NE * IN_DIM];   // transposed: sW[e*1024 + i]
    int tid = threadIdx.x;
    for (int idx = tid; idx < NE * IN_DIM; idx += 1024) {
        int i = idx >> 3, e = idx & 7;
        sW[e * IN_DIM + i] = Wg[idx];
    }
    __syncthreads();
    int w = tid >> 5, lane = tid & 31;
    int n = blockIdx.x * 32 + w;
    float acc[NE];
#pragma unroll
    for (int e = 0; e < NE; e++) acc[e] = 0.f;
    const float* xr = x + (size_t)n * IN_DIM;
    for (int i = lane; i < IN_DIM; i += 32) {
        float xv = xr[i];
#pragma unroll
        for (int e = 0; e < NE; e++) acc[e] += xv * sW[e * IN_DIM + i];
    }
#pragma unroll
    for (int e = 0; e < NE; e++) {
#pragma unroll
        for (int off = 16; off; off >>= 1)
            acc[e] += __shfl_xor_sync(0xffffffffu, acc[e], off);
    }
    if (lane == 0) {
        float v[NE], m = -1e30f;
#pragma unroll
        for (int e = 0; e < NE; e++) { v[e] = acc[e] + bg[e]; m = fmaxf(m, v[e]); }
        float s = 0.f;
#pragma unroll
        for (int e = 0; e < NE; e++) { v[e] = expf(v[e] - m); s += v[e]; }
        float inv = 1.0f / s;
#pragma unroll
        for (int e = 0; e < NE; e++) g_gates[n * NE + e] = v[e] * inv;
    }
}

// ---------------- kernel 2: We fp32 -> fp16 copy (layout preserved) ----------------
__global__ __launch_bounds__(256) void convert_kernel(const float* __restrict__ We) {
    int total = KTOT * OUT_DIM / 8;
    for (int idx = blockIdx.x * blockDim.x + threadIdx.x; idx < total;
         idx += gridDim.x * blockDim.x) {
        const float4* s = (const float4*)We + (size_t)idx * 2;
        float4 a = s[0], b = s[1];
        uint4 w;
        w.x = packh2(a.x, a.y); w.y = packh2(a.z, a.w);
        w.z = packh2(b.x, b.y); w.w = packh2(b.z, b.w);
        *(uint4*)(g_Wh + (size_t)idx * 8) = w;
    }
}

// ---------------- kernel 3: fused fp16 mma GEMM, ldmatrix A + ldmatrix.trans B ----------------
__global__ __launch_bounds__(256, 2) void moe_mma_kernel(const float* __restrict__ x,
                                                         const float* __restrict__ be,
                                                         float* __restrict__ out) {
    extern __shared__ __align__(16) char smem[];
    const uint32_t aBase = smem_u32(smem);
    const uint32_t bBase = aBase + SB_BASE;
    float* sg = (float*)(smem + SG_BASE);

    int tid = threadIdx.x;
    int m0 = blockIdx.y * BM, o0 = blockIdx.x * BN;

    for (int i = tid; i < BM * NE; i += 256) sg[i] = g_gates[m0 * NE + i];
    __syncthreads();

    // ---- A producer mapping (block-contiguous 8x8 fp16 matrices, k8-parity swizzle) ----
    const int row = tid >> 1, h = tid & 1;
    const int m8p = row >> 3, r8p = row & 7;
    const uint32_t aoffQ0 = (uint32_t)(((m8p * 4 + h) * 128) + (((r8p + 4 * h) & 7) * 16));
    const uint32_t aoffQ1 = (uint32_t)(((m8p * 4 + h + 2) * 128) + (((r8p + 4 * (h + 2)) & 7) * 16));
    const float* xrow = x + (size_t)(m0 + row) * IN_DIM;

    // ---- B producer mapping: plain fp16 [k][n] rows, XOR-swizzled 16B cols ----
    const int kr = tid >> 3, seg = tid & 7;     // kr 0..31, two 16B slots: seg, seg+8
    const uint32_t bd0 = bswz(kr, seg), bd1 = bswz(kr, seg + 8);

    auto produceB = [&](int st, int c) {
        uint32_t sbase = bBase + (uint32_t)st * SB_STAGE;
        if (c < 256) {
            int ic = c >> 3, e = c & 7;
            const __half* src = g_Wh + (size_t)(e * 1024 + ic * 32 + kr) * OUT_DIM + o0 + seg * 8;
            asm volatile("cp.async.cg.shared.global [%0], [%1], 16;" :: "r"(sbase + bd0), "l"(src));
            asm volatile("cp.async.cg.shared.global [%0], [%1], 16;" :: "r"(sbase + bd1), "l"(src + 64));
        } else {
            if (kr < 8) {
                const float* s0 = be + (size_t)kr * OUT_DIM + o0 + seg * 8;
                float4 a = *(const float4*)s0, b = *(const float4*)(s0 + 4);
                asm volatile("st.shared.v4.b32 [%0], {%1,%2,%3,%4};" :: "r"(sbase + bd0),
                             "r"(packh2(a.x, a.y)), "r"(packh2(a.z, a.w)),
                             "r"(packh2(b.x, b.y)), "r"(packh2(b.z, b.w)));
                a = *(const float4*)(s0 + 64); b = *(const float4*)(s0 + 68);
                asm volatile("st.shared.v4.b32 [%0], {%1,%2,%3,%4};" :: "r"(sbase + bd1),
                             "r"(packh2(a.x, a.y)), "r"(packh2(a.z, a.w)),
                             "r"(packh2(b.x, b.y)), "r"(packh2(b.z, b.w)));
            } else {
                asm volatile("st.shared.v4.b32 [%0], {%1,%1,%1,%1};" :: "r"(sbase + bd0), "r"(0u));
                asm volatile("st.shared.v4.b32 [%0], {%1,%1,%1,%1};" :: "r"(sbase + bd1), "r"(0u));
            }
        }
        asm volatile("cp.async.commit_group;");
    };
    auto produceA = [&](int st, int c) {
        uint32_t base = aBase + (uint32_t)st * SA_STAGE;
        if (c < 256) {
            int ic = c >> 3, e = c & 7;
            float ge = sg[row * NE + e];
            {
                const float* p = xrow + ic * 32 + h * 8;
                float4 v0 = *(const float4*)p, v1 = *(const float4*)(p + 4);
                asm volatile("st.shared.v4.b32 [%0], {%1,%2,%3,%4};" :: "r"(base + aoffQ0),
                             "r"(packh2(v0.x * ge, v0.y * ge)), "r"(packh2(v0.z * ge, v0.w * ge)),
                             "r"(packh2(v1.x * ge, v1.y * ge)), "r"(packh2(v1.z * ge, v1.w * ge)));
            }
            {
                const float* p = xrow + ic * 32 + 16 + h * 8;
                float4 v0 = *(const float4*)p, v1 = *(const float4*)(p + 4);
                asm volatile("st.shared.v4.b32 [%0], {%1,%2,%3,%4};" :: "r"(base + aoffQ1),
                             "r"(packh2(v0.x * ge, v0.y * ge)), "r"(packh2(v0.z * ge, v0.w * ge)),
                             "r"(packh2(v1.x * ge, v1.y * ge)), "r"(packh2(v1.z * ge, v1.w * ge)));
            }
        } else {
            if (h == 0) {
                const float* g = &sg[row * NE];
                asm volatile("st.shared.v4.b32 [%0], {%1,%2,%3,%4};" :: "r"(base + aoffQ0),
                             "r"(packh2(g[0], g[1])), "r"(packh2(g[2], g[3])),
                             "r"(packh2(g[4], g[5])), "r"(packh2(g[6], g[7])));
            } else {
                asm volatile("st.shared.v4.b32 [%0], {%1,%1,%1,%1};" :: "r"(base + aoffQ0), "r"(0u));
            }
            asm volatile("st.shared.v4.b32 [%0], {%1,%1,%1,%1};" :: "r"(base + aoffQ1), "r"(0u));
        }
    };

    // ---- accumulators / warp mapping ----
    float acc[4][4][4];
#pragma unroll
    for (int mi = 0; mi < 4; mi++)
#pragma unroll
        for (int ni = 0; ni < 4; ni++)
#pragma unroll
            for (int q = 0; q < 4; q++) acc[mi][ni][q] = 0.f;

    int wid = tid >> 5, lane = tid & 31;
    int wm = (wid & 1) * 64, wn = (wid >> 1) * 32;
    int lr = lane >> 2, lc = lane & 3;
    const int wmBlk = (wid & 1) * 8;
    const int wn8 = wn >> 3;

    // A ldmatrix lane constant
    const int jm = (lane >> 3) & 1, jk = lane >> 4, rr = lane & 7;
    const uint32_t aLane = (uint32_t)((jm * 4 + jk) * 128 + (((rr + 4 * jk) & 7) * 16));
    // B ldmatrix.trans lane constants: group jb covers (ni offset jb>>1, k8 offset jb&1)
    const int jb = lane >> 3, rb = lane & 7;
    const int kb = 8 * (jb & 1) + rb;        // k-row within the k16 group
    const int nb = jb >> 1;                  // ni offset within the instr's ni pair

    auto compute = [&](int st) {
        const uint32_t A = aBase + (uint32_t)st * SA_STAGE + aLane;
        const uint32_t B = bBase + (uint32_t)st * SB_STAGE;
#pragma unroll
        for (int ks = 0; ks < 2; ks++) {
            uint32_t bf[4][2];
#pragma unroll
            for (int p = 0; p < 2; p++) {
                int krL = 16 * ks + kb;
                int col16 = wn8 + 2 * p + nb;
                uint32_t addr = B + bswz(krL, col16);
                asm volatile("ldmatrix.sync.aligned.m8n8.x4.trans.shared.b16 {%0,%1,%2,%3}, [%4];"
                             : "=r"(bf[2 * p][0]), "=r"(bf[2 * p][1]),
                               "=r"(bf[2 * p + 1][0]), "=r"(bf[2 * p + 1][1])
                             : "r"(addr));
            }
#pragma unroll
            for (int mi = 0; mi < 4; mi++) {
                uint32_t a0, a1, a2, a3;
                uint32_t addr = A + (uint32_t)((((wmBlk + 2 * mi) * 4) + 2 * ks) * 128);
                asm volatile("ldmatrix.sync.aligned.m8n8.x4.shared.b16 {%0,%1,%2,%3}, [%4];"
                             : "=r"(a0), "=r"(a1), "=r"(a2), "=r"(a3) : "r"(addr));
#pragma unroll
                for (int ni = 0; ni < 4; ni++)
                    asm volatile(
                        "mma.sync.aligned.m16n8k16.row.col.f32.f16.f16.f32 "
                        "{%0,%1,%2,%3}, {%4,%5,%6,%7}, {%8,%9}, {%0,%1,%2,%3};"
                        : "+f"(acc[mi][ni][0]), "+f"(acc[mi][ni][1]),
                          "+f"(acc[mi][ni][2]), "+f"(acc[mi][ni][3])
                        : "r"(a0), "r"(a1), "r"(a2), "r"(a3),
                          "r"(bf[ni][0]), "r"(bf[ni][1]));
            }
        }
    };

    // ---- prologue: fill stages 0..2 ----
#pragma unroll
    for (int s = 0; s < STAGES - 1; s++) {
        produceA(s, s);
        produceB(s, s);
    }

    // ---- main loop: c = 0..253, produce chunk c+3 ----
    int st_c = 0, st_p = STAGES - 1;
#pragma unroll 1
    for (int c = 0; c < NCHUNK - STAGES + 1; c++) {          // 0..253
        asm volatile("cp.async.wait_group %0;" :: "n"(STAGES - 2) : "memory");
        __syncthreads();
        produceA(st_p, c + STAGES - 1);
        produceB(st_p, c + STAGES - 1);
        compute(st_c);
        st_c = (st_c == STAGES - 1) ? 0 : st_c + 1;
        st_p = (st_p == STAGES - 1) ? 0 : st_p + 1;
    }
    // ---- tail: chunks 254, 255, 256 resident ----
    asm volatile("cp.async.wait_group 0;" ::: "memory");
    __syncthreads();
#pragma unroll
    for (int t = 0; t < STAGES - 1; t++) {
        compute(st_c);
        st_c = (st_c == STAGES - 1) ? 0 : st_c + 1;
    }

    // ---- epilogue: pure store (bias folded into GEMM) ----
#pragma unroll
    for (int mi = 0; mi < 4; mi++) {
        int r = m0 + wm + mi * 16 + lr;
#pragma unroll
        for (int ni = 0; ni < 4; ni++) {
            int cc = o0 + wn + ni * 8 + lc * 2;
            *(float2*)(out + (size_t)r * OUT_DIM + cc) =
                make_float2(acc[mi][ni][0], acc[mi][ni][1]);
            *(float2*)(out + (size_t)(r + 8) * OUT_DIM + cc) =
                make_float2(acc[mi][ni][2], acc[mi][ni][3]);
        }
    }
}

// ---------------- launch ----------------
extern "C" void kernel_launch(void* const* d_in, const int* in_sizes, int n_in,
                              void* d_out, int out_size) {
    const float* x  = (const float*)d_in[0];
    const float* We = (const float*)d_in[1];
    const float* be = (const float*)d_in[2];
    const float* Wg = (const float*)d_in[3];
    const float* bg = (const float*)d_in[4];
    float* out = (float*)d_out;

    cudaFuncSetAttribute(moe_mma_kernel, cudaFuncAttributeMaxDynamicSharedMemorySize, SMEM_BYTES);

    gate_kernel<<<NTOK / 32, 1024>>>(x, Wg, bg);
    convert_kernel<<<2048, 256>>>(We);
    moe_mma_kernel<<<dim3(OUT_DIM / BN, NTOK / BM), 256, SMEM_BYTES>>>(x, be, out);
}